// round 5
// baseline (speedup 1.0000x reference)
#include <cuda_runtime.h>
#include <math.h>

#define Nn 16384
#define Dd 256
#define NC 1024   // cols: [0,256)=q | [256,512)=C_pd | [512,768)=C_sd | [768,1024)=Delta

__device__ float g_B[Dd * NC];   // combined weights [K=256, NC]
__device__ float g_S[(size_t)Nn * NC];

// ---------------- packed f32x2 helpers ----------------
__device__ __forceinline__ unsigned long long ffma2(unsigned long long a,
                                                    unsigned long long b,
                                                    unsigned long long c) {
    unsigned long long d;
    asm("fma.rn.f32x2 %0, %1, %2, %3;" : "=l"(d) : "l"(a), "l"(b), "l"(c));
    return d;
}
__device__ __forceinline__ unsigned long long dup2(float a) {
    unsigned long long r;
    asm("mov.b64 %0, {%1, %1};" : "=l"(r) : "f"(a));
    return r;
}
__device__ __forceinline__ float2 unpk(unsigned long long v) {
    float2 f;
    asm("mov.b64 {%0, %1}, %2;" : "=f"(f.x), "=f"(f.y) : "l"(v));
    return f;
}

// ---------------------------------------------------------------------------
// Kernel 0: combined weight matrix
// ---------------------------------------------------------------------------
__global__ void combine_kernel(const float* __restrict__ Wa,
                               const float* __restrict__ Wp,
                               const float* __restrict__ Wsuc,
                               const float* __restrict__ Wsame,
                               const float* __restrict__ Wdiff) {
    int idx = blockIdx.x * blockDim.x + threadIdx.x;
    if (idx >= Dd * NC) return;
    int e = idx / NC;
    int c = idx % NC;
    int d = c & 255;
    float v;
    if (c < 256)      v = Wa[e * 256 + c];
    else if (c < 512) v = Wp[e * 256 + d]   + Wdiff[e * 256 + d];
    else if (c < 768) v = Wsuc[e * 256 + d] + Wdiff[e * 256 + d];
    else              v = Wsame[e * 256 + d] - Wdiff[e * 256 + d];
    g_B[idx] = v;
}

// ---------------------------------------------------------------------------
// Kernel 1: SGEMM  g_S[16384,1024] = x[16384,256] @ g_B[256,1024]  (FFMA2)
// ---------------------------------------------------------------------------
#define BM 128
#define BN 128
#define BK 16
#define TM 8
#define TN 8

__global__ __launch_bounds__(256, 2) void sgemm_kernel(const float* __restrict__ A) {
    __shared__ float2 As2[BK][BM];          // A value duplicated (a,a)
    __shared__ float  Bs[BK][BN];
    const int K = Dd, N = NC;

    int bx = blockIdx.x, by = blockIdx.y;
    int tid = threadIdx.x;
    int lane = tid & 31;

    const float* Ablk = A + (size_t)by * BM * K;
    const float* Bblk = g_B + bx * BN;
    float* Cblk = g_S + (size_t)by * BM * N + bx * BN;

    int aRow = tid >> 2;            // 0..63
    int aCol4 = (tid & 3) * 4;
    int bRow = tid >> 5;            // 0..7
    int bCol4 = (tid & 31) * 4;

    int tRow = (tid >> 4) * TM;
    int tCol = (tid & 15) * TN;
    int rot = (lane >> 2) & 3;      // bank-conflict-avoiding rotation for Bs reads

    unsigned long long acc2[TM][TN / 2];
#pragma unroll
    for (int i = 0; i < TM; i++)
#pragma unroll
        for (int j = 0; j < TN / 2; j++) acc2[i][j] = 0ull;

    for (int k0 = 0; k0 < K; k0 += BK) {
#pragma unroll
        for (int r = 0; r < 2; r++) {
            int row = aRow + r * 64;
            float4 v = *(const float4*)(Ablk + (size_t)row * K + k0 + aCol4);
            As2[aCol4 + 0][row] = make_float2(v.x, v.x);
            As2[aCol4 + 1][row] = make_float2(v.y, v.y);
            As2[aCol4 + 2][row] = make_float2(v.z, v.z);
            As2[aCol4 + 3][row] = make_float2(v.w, v.w);
        }
#pragma unroll
        for (int r = 0; r < 2; r++) {
            int row = bRow + r * 8;
            float4 v = *(const float4*)(Bblk + (size_t)(k0 + row) * N + bCol4);
            *(float4*)(&Bs[row][bCol4]) = v;
        }
        __syncthreads();
#pragma unroll
        for (int kk = 0; kk < BK; kk++) {
            unsigned long long regM[TM], regN[TN / 2];
            const unsigned long long* ap = (const unsigned long long*)&As2[kk][tRow];
#pragma unroll
            for (int i = 0; i < TM; i++) regM[i] = ap[i];
#pragma unroll
            for (int t = 0; t < TN / 2; t++) {
                int j2 = (t + rot) & 3;
                regN[j2] = *(const unsigned long long*)&Bs[kk][tCol + 2 * j2];
            }
#pragma unroll
            for (int i = 0; i < TM; i++)
#pragma unroll
                for (int j = 0; j < TN / 2; j++)
                    acc2[i][j] = ffma2(regM[i], regN[j], acc2[i][j]);
        }
        __syncthreads();
    }
#pragma unroll
    for (int i = 0; i < TM; i++) {
        float* Crow = Cblk + (size_t)(tRow + i) * N + tCol;
        float2 a0 = unpk(acc2[i][0]), a1 = unpk(acc2[i][1]);
        float2 a2 = unpk(acc2[i][2]), a3 = unpk(acc2[i][3]);
        *(float4*)(Crow)     = make_float4(a0.x, a0.y, a1.x, a1.y);
        *(float4*)(Crow + 4) = make_float4(a2.x, a2.y, a3.x, a3.y);
    }
}

// ---------------------------------------------------------------------------
// Kernel 2: 8 utterances per block — dots, softmax, banded agg, log_softmax
// ---------------------------------------------------------------------------
#define JJN 135   // band rows jj = j - (n0-64), jj in [0, 134]

__global__ __launch_bounds__(256) void attn_agg_kernel(const float* __restrict__ x,
                                                       const int* __restrict__ spk,
                                                       float* __restrict__ out) {
    int n0 = blockIdx.x * 8;
    int jlo = n0 - 64;
    int tid = threadIdx.x;
    int lane = tid & 31, warp = tid >> 5;

    __shared__ float q_s[8][256];
    __shared__ float raw_s[8][JJN + 1];
    __shared__ __align__(16) float w_s[JJN + 1][24];  // [0:8)=a_pd [8:16)=a_sd [16:24)=a_sm
    __shared__ float red[8][8];
    __shared__ float mx[8], lsz[8];

#pragma unroll
    for (int r = 0; r < 8; r++)
        q_s[r][tid] = g_S[(size_t)(n0 + r) * NC + tid];
    for (int i = tid; i < (JJN + 1) * 24; i += 256)
        ((float*)w_s)[i] = 0.f;
    __syncthreads();

    // --- Phase A: raw[n][slot] = x[j] . q[n] for band rows
    for (int jj = warp; jj < JJN; jj += 8) {
        int j = jlo + jj;
        bool vj = ((unsigned)j < (unsigned)Nn);
        float xr[8];
        if (vj) {
            const float* xp = x + (size_t)j * 256 + lane;
#pragma unroll
            for (int t = 0; t < 8; t++) xr[t] = xp[32 * t];
        }
#pragma unroll
        for (int dn = 0; dn < 8; dn++) {
            int slot = jj - dn;
            if (slot < 0 || slot >= 128) continue;
            float acc = 0.f;
            if (vj) {
#pragma unroll
                for (int t = 0; t < 8; t++) acc += xr[t] * q_s[dn][lane + 32 * t];
#pragma unroll
                for (int o = 16; o > 0; o >>= 1)
                    acc += __shfl_xor_sync(0xffffffffu, acc, o);
            }
            if (lane == 0) raw_s[dn][jj] = acc;   // 0 when j out of range (padded slot)
        }
    }
    __syncthreads();

    // --- Phase B: softmax per n (warp dn) + masked weights
    {
        int dn = warp;
        int n = n0 + dn;
        float v[4];
#pragma unroll
        for (int k = 0; k < 4; k++) v[k] = raw_s[dn][lane + 32 * k + dn];
        float m = fmaxf(fmaxf(v[0], v[1]), fmaxf(v[2], v[3]));
#pragma unroll
        for (int o = 16; o > 0; o >>= 1) m = fmaxf(m, __shfl_xor_sync(0xffffffffu, m, o));
        float z = expf(v[0] - m) + expf(v[1] - m) + expf(v[2] - m) + expf(v[3] - m);
#pragma unroll
        for (int o = 16; o > 0; o >>= 1) z += __shfl_xor_sync(0xffffffffu, z, o);
        float inv_z = 1.f / z;
        int sn = spk[n];
#pragma unroll
        for (int k = 0; k < 4; k++) {
            int slot = lane + 32 * k;
            int jj = slot + dn;
            int j = jlo + jj;
            bool vjj = ((unsigned)j < (unsigned)Nn);
            float a = vjj ? expf(v[k] - m) * inv_z : 0.f;
            bool pred = (slot >= 64);
            bool same = vjj && (spk[j] == sn);
            w_s[jj][dn]      = pred ? a : 0.f;
            w_s[jj][8 + dn]  = pred ? 0.f : a;
            w_s[jj][16 + dn] = same ? a : 0.f;
        }
    }
    __syncthreads();

    // --- Phase C: banded aggregation, thread = dim d, FFMA2 over n-pairs
    int d = tid;
    unsigned long long accA[4] = {0ull, 0ull, 0ull, 0ull};
    for (int jj = 0; jj < JJN; jj++) {
        int j = jlo + jj;
        if ((unsigned)j >= (unsigned)Nn) continue;
        const float* Srow = g_S + (size_t)j * NC;
        bool npd = (jj >= 64);   // some slot >= 64 exists
        bool nsd = (jj < 71);    // some slot < 64 exists
        unsigned long long dlt2 = dup2(Srow[768 + d]);
        const unsigned long long* wp = (const unsigned long long*)&w_s[jj][0];
        if (npd) {
            unsigned long long cpd2 = dup2(Srow[256 + d]);
#pragma unroll
            for (int p = 0; p < 4; p++) accA[p] = ffma2(wp[p], cpd2, accA[p]);
        }
        if (nsd) {
            unsigned long long csd2 = dup2(Srow[512 + d]);
#pragma unroll
            for (int p = 0; p < 4; p++) accA[p] = ffma2(wp[4 + p], csd2, accA[p]);
        }
#pragma unroll
        for (int p = 0; p < 4; p++) accA[p] = ffma2(wp[8 + p], dlt2, accA[p]);
    }

    float h[8];
#pragma unroll
    for (int p = 0; p < 4; p++) {
        float2 t = unpk(accA[p]);
        h[2 * p] = t.x; h[2 * p + 1] = t.y;
    }

    // --- Phase D: log_softmax over d for each of the 8 rows
#pragma unroll
    for (int r = 0; r < 8; r++) {
        float m = h[r];
#pragma unroll
        for (int o = 16; o > 0; o >>= 1) m = fmaxf(m, __shfl_xor_sync(0xffffffffu, m, o));
        if (lane == 0) red[warp][r] = m;
    }
    __syncthreads();
    {
        float m = (lane < 8) ? red[lane][warp] : -3.4e38f;
#pragma unroll
        for (int o = 4; o > 0; o >>= 1) m = fmaxf(m, __shfl_xor_sync(0xffffffffu, m, o));
        if (lane == 0) mx[warp] = m;
    }
    __syncthreads();
#pragma unroll
    for (int r = 0; r < 8; r++) {
        float s = expf(h[r] - mx[r]);
#pragma unroll
        for (int o = 16; o > 0; o >>= 1) s += __shfl_xor_sync(0xffffffffu, s, o);
        if (lane == 0) red[warp][r] = s;
    }
    __syncthreads();
    {
        float s = (lane < 8) ? red[lane][warp] : 0.f;
#pragma unroll
        for (int o = 4; o > 0; o >>= 1) s += __shfl_xor_sync(0xffffffffu, s, o);
        if (lane == 0) lsz[warp] = logf(s);
    }
    __syncthreads();
#pragma unroll
    for (int r = 0; r < 8; r++)
        out[(size_t)(n0 + r) * 256 + d] = h[r] - mx[r] - lsz[r];
}

// ---------------------------------------------------------------------------
extern "C" void kernel_launch(void* const* d_in, const int* in_sizes, int n_in,
                              void* d_out, int out_size) {
    const float* x     = (const float*)d_in[0];
    const int*   spk   = (const int*)d_in[1];
    const float* Wa    = (const float*)d_in[2];
    const float* Wp    = (const float*)d_in[3];
    const float* Wsuc  = (const float*)d_in[4];
    const float* Wsame = (const float*)d_in[5];
    const float* Wdiff = (const float*)d_in[6];
    float* out = (float*)d_out;

    combine_kernel<<<(Dd * NC + 255) / 256, 256>>>(Wa, Wp, Wsuc, Wsame, Wdiff);

    dim3 gg(NC / BN, Nn / BM);
    sgemm_kernel<<<gg, 256>>>(x);

    attn_agg_kernel<<<Nn / 8, 256>>>(x, spk, out);
}

// round 7
// speedup vs baseline: 3.2074x; 3.2074x over previous
#include <cuda_runtime.h>
#include <math.h>

#define Nn 16384
#define Dd 256
#define NC 1024   // cols: [0,256)=q | [256,512)=C_pd | [512,768)=C_sd | [768,1024)=Delta

__device__ float g_B[Dd * NC];
__device__ float g_S[(size_t)Nn * NC];

typedef unsigned long long ull;

// ---------------- packed f32x2 helpers ----------------
__device__ __forceinline__ ull ffma2(ull a, ull b, ull c) {
    ull d;
    asm("fma.rn.f32x2 %0, %1, %2, %3;" : "=l"(d) : "l"(a), "l"(b), "l"(c));
    return d;
}
__device__ __forceinline__ ull dup2(float a) {
    ull r;
    asm("mov.b64 %0, {%1, %1};" : "=l"(r) : "f"(a));
    return r;
}
__device__ __forceinline__ ull pack2(float x, float y) {
    ull r;
    asm("mov.b64 %0, {%1, %2};" : "=l"(r) : "f"(x), "f"(y));
    return r;
}
__device__ __forceinline__ float2 unpk(ull v) {
    float2 f;
    asm("mov.b64 {%0, %1}, %2;" : "=f"(f.x), "=f"(f.y) : "l"(v));
    return f;
}

// ---------------------------------------------------------------------------
// Kernel 0: combined weight matrix
// ---------------------------------------------------------------------------
__global__ void combine_kernel(const float* __restrict__ Wa,
                               const float* __restrict__ Wp,
                               const float* __restrict__ Wsuc,
                               const float* __restrict__ Wsame,
                               const float* __restrict__ Wdiff) {
    int idx = blockIdx.x * blockDim.x + threadIdx.x;
    if (idx >= Dd * NC) return;
    int e = idx / NC;
    int c = idx % NC;
    int d = c & 255;
    float v;
    if (c < 256)      v = Wa[e * 256 + c];
    else if (c < 512) v = Wp[e * 256 + d]   + Wdiff[e * 256 + d];
    else if (c < 768) v = Wsuc[e * 256 + d] + Wdiff[e * 256 + d];
    else              v = Wsame[e * 256 + d] - Wdiff[e * 256 + d];
    g_B[idx] = v;
}

// ---------------------------------------------------------------------------
// Kernel 1: SGEMM  g_S[16384,1024] = x[16384,256] @ g_B[256,1024]  (FFMA2)
// ---------------------------------------------------------------------------
#define BM 128
#define BN 128
#define BK 16
#define TM 8
#define TN 8

__global__ __launch_bounds__(256, 2) void sgemm_kernel(const float* __restrict__ A) {
    __shared__ float2 As2[BK][BM];   // A value duplicated (a,a)
    __shared__ float  Bs[BK][BN];
    const int K = Dd, N = NC;

    int bx = blockIdx.x, by = blockIdx.y;
    int tid = threadIdx.x;

    const float* Ablk = A + (size_t)by * BM * K;
    const float* Bblk = g_B + bx * BN;
    float* Cblk = g_S + (size_t)by * BM * N + bx * BN;

    int aRow = tid >> 2;            // 0..63
    int aCol4 = (tid & 3) * 4;
    int bRow = tid >> 5;            // 0..7
    int bCol4 = (tid & 31) * 4;

    int tRow = (tid >> 4) * TM;
    int tCol = (tid & 15) * TN;

    ull acc2[TM][TN / 2];
#pragma unroll
    for (int i = 0; i < TM; i++)
#pragma unroll
        for (int j = 0; j < TN / 2; j++) acc2[i][j] = 0ull;

    for (int k0 = 0; k0 < K; k0 += BK) {
#pragma unroll
        for (int r = 0; r < 2; r++) {
            int row = aRow + r * 64;
            float4 v = *(const float4*)(Ablk + (size_t)row * K + k0 + aCol4);
            As2[aCol4 + 0][row] = make_float2(v.x, v.x);
            As2[aCol4 + 1][row] = make_float2(v.y, v.y);
            As2[aCol4 + 2][row] = make_float2(v.z, v.z);
            As2[aCol4 + 3][row] = make_float2(v.w, v.w);
        }
#pragma unroll
        for (int r = 0; r < 2; r++) {
            int row = bRow + r * 8;
            float4 v = *(const float4*)(Bblk + (size_t)(k0 + row) * N + bCol4);
            *(float4*)(&Bs[row][bCol4]) = v;
        }
        __syncthreads();
#pragma unroll
        for (int kk = 0; kk < BK; kk++) {
            ull regM[TM], regN[TN / 2];
            const ull* ap = (const ull*)&As2[kk][tRow];
#pragma unroll
            for (int i = 0; i < TM; i++) regM[i] = ap[i];
#pragma unroll
            for (int t = 0; t < TN / 2; t++)
                regN[t] = *(const ull*)&Bs[kk][tCol + 2 * t];   // STATIC index
#pragma unroll
            for (int i = 0; i < TM; i++)
#pragma unroll
                for (int j = 0; j < TN / 2; j++)
                    acc2[i][j] = ffma2(regM[i], regN[j], acc2[i][j]);
        }
        __syncthreads();
    }
#pragma unroll
    for (int i = 0; i < TM; i++) {
        float* Crow = Cblk + (size_t)(tRow + i) * N + tCol;
        float2 a0 = unpk(acc2[i][0]), a1 = unpk(acc2[i][1]);
        float2 a2 = unpk(acc2[i][2]), a3 = unpk(acc2[i][3]);
        *(float4*)(Crow)     = make_float4(a0.x, a0.y, a1.x, a1.y);
        *(float4*)(Crow + 4) = make_float4(a2.x, a2.y, a3.x, a3.y);
    }
}

// ---------------------------------------------------------------------------
// Kernel 2: 8 utterances per block
// ---------------------------------------------------------------------------
#define JJN 135

__global__ __launch_bounds__(256) void attn_agg_kernel(const float* __restrict__ x,
                                                       const int* __restrict__ spk,
                                                       float* __restrict__ out) {
    int n0 = blockIdx.x * 8;
    int jlo = n0 - 64;
    int tid = threadIdx.x;
    int lane = tid & 31, warp = tid >> 5;

    __shared__ float q_s[8][256];
    __shared__ float raw_s[8][JJN + 1];
    __shared__ __align__(16) float w_s[JJN + 1][24];  // [0:8)=pd [8:16)=sd [16:24)=same
    __shared__ float red[8][8];
    __shared__ float mx[8], lsz[8];

#pragma unroll
    for (int r = 0; r < 8; r++)
        q_s[r][tid] = g_S[(size_t)(n0 + r) * NC + tid];
    for (int i = tid; i < (JJN + 1) * 24; i += 256)
        ((float*)w_s)[i] = 0.f;
    __syncthreads();

    // --- Phase A: raw[n][slot] = x[j] . q[n]
    for (int jj = warp; jj < JJN; jj += 8) {
        int j = jlo + jj;
        bool vj = ((unsigned)j < (unsigned)Nn);
        ull xr2[4];
        if (vj) {
            const float2* xp2 = (const float2*)(x + (size_t)j * 256) + lane;
#pragma unroll
            for (int t = 0; t < 4; t++) {
                float2 v = xp2[32 * t];
                xr2[t] = pack2(v.x, v.y);
            }
        }
#pragma unroll
        for (int dn = 0; dn < 8; dn++) {
            int slot = jj - dn;
            if (slot < 0 || slot >= 128) continue;
            float acc = 0.f;
            if (vj) {
                const ull* q2 = (const ull*)q_s[dn];
                ull a2 = 0ull;
#pragma unroll
                for (int t = 0; t < 4; t++) a2 = ffma2(xr2[t], q2[lane + 32 * t], a2);
                float2 p = unpk(a2);
                acc = p.x + p.y;
#pragma unroll
                for (int o = 16; o > 0; o >>= 1)
                    acc += __shfl_xor_sync(0xffffffffu, acc, o);
            }
            if (lane == 0) raw_s[dn][jj] = acc;   // 0 for padded slot
        }
    }
    __syncthreads();

    // --- Phase B: softmax per n (warp = dn) + masked weights
    {
        int dn = warp;
        int n = n0 + dn;
        float v[4];
#pragma unroll
        for (int k = 0; k < 4; k++) v[k] = raw_s[dn][lane + 32 * k + dn];
        float m = fmaxf(fmaxf(v[0], v[1]), fmaxf(v[2], v[3]));
#pragma unroll
        for (int o = 16; o > 0; o >>= 1) m = fmaxf(m, __shfl_xor_sync(0xffffffffu, m, o));
        float z = expf(v[0] - m) + expf(v[1] - m) + expf(v[2] - m) + expf(v[3] - m);
#pragma unroll
        for (int o = 16; o > 0; o >>= 1) z += __shfl_xor_sync(0xffffffffu, z, o);
        float inv_z = 1.f / z;
        int sn = spk[n];
#pragma unroll
        for (int k = 0; k < 4; k++) {
            int slot = lane + 32 * k;
            int jj = slot + dn;
            int j = jlo + jj;
            bool vjj = ((unsigned)j < (unsigned)Nn);
            float a = vjj ? expf(v[k] - m) * inv_z : 0.f;
            bool pred = (slot >= 64);
            bool same = vjj && (spk[j] == sn);
            w_s[jj][dn]      = pred ? a : 0.f;
            w_s[jj][8 + dn]  = pred ? 0.f : a;
            w_s[jj][16 + dn] = same ? a : 0.f;
        }
    }
    __syncthreads();

    // --- Phase C: banded aggregation (thread = dim d), range-split, branch-free
    int d = tid;
    ull acc[4] = {0ull, 0ull, 0ull, 0ull};
    int vlo = (jlo < 0) ? -jlo : 0;                       // first valid jj
    int vhi = (Nn - jlo < JJN) ? (Nn - jlo) : JJN;        // one past last valid jj

    // region 1: jj in [vlo, min(64,vhi))  -> suc + delta
    {
        int e = (vhi < 64) ? vhi : 64;
#pragma unroll 4
        for (int jj = vlo; jj < e; jj++) {
            const float* Srow = g_S + (size_t)(jlo + jj) * NC;
            ull sd2 = dup2(Srow[512 + d]);
            ull dl2 = dup2(Srow[768 + d]);
            const ulonglong2* wq = (const ulonglong2*)&w_s[jj][0];
            ulonglong2 w2 = wq[2], w3 = wq[3], w4 = wq[4], w5 = wq[5];
            acc[0] = ffma2(w2.x, sd2, acc[0]); acc[1] = ffma2(w2.y, sd2, acc[1]);
            acc[2] = ffma2(w3.x, sd2, acc[2]); acc[3] = ffma2(w3.y, sd2, acc[3]);
            acc[0] = ffma2(w4.x, dl2, acc[0]); acc[1] = ffma2(w4.y, dl2, acc[1]);
            acc[2] = ffma2(w5.x, dl2, acc[2]); acc[3] = ffma2(w5.y, dl2, acc[3]);
        }
    }
    // region 2: jj in [max(64,vlo), min(71,vhi))  -> pred + suc + delta
    {
        int s = (vlo > 64) ? vlo : 64;
        int e = (vhi < 71) ? vhi : 71;
#pragma unroll
        for (int jj = s; jj < e; jj++) {
            const float* Srow = g_S + (size_t)(jlo + jj) * NC;
            ull pd2 = dup2(Srow[256 + d]);
            ull sd2 = dup2(Srow[512 + d]);
            ull dl2 = dup2(Srow[768 + d]);
            const ulonglong2* wq = (const ulonglong2*)&w_s[jj][0];
            ulonglong2 w0 = wq[0], w1 = wq[1], w2 = wq[2], w3 = wq[3], w4 = wq[4], w5 = wq[5];
            acc[0] = ffma2(w0.x, pd2, acc[0]); acc[1] = ffma2(w0.y, pd2, acc[1]);
            acc[2] = ffma2(w1.x, pd2, acc[2]); acc[3] = ffma2(w1.y, pd2, acc[3]);
            acc[0] = ffma2(w2.x, sd2, acc[0]); acc[1] = ffma2(w2.y, sd2, acc[1]);
            acc[2] = ffma2(w3.x, sd2, acc[2]); acc[3] = ffma2(w3.y, sd2, acc[3]);
            acc[0] = ffma2(w4.x, dl2, acc[0]); acc[1] = ffma2(w4.y, dl2, acc[1]);
            acc[2] = ffma2(w5.x, dl2, acc[2]); acc[3] = ffma2(w5.y, dl2, acc[3]);
        }
    }
    // region 3: jj in [max(71,vlo), vhi)  -> pred + delta
    {
        int s = (vlo > 71) ? vlo : 71;
#pragma unroll 4
        for (int jj = s; jj < vhi; jj++) {
            const float* Srow = g_S + (size_t)(jlo + jj) * NC;
            ull pd2 = dup2(Srow[256 + d]);
            ull dl2 = dup2(Srow[768 + d]);
            const ulonglong2* wq = (const ulonglong2*)&w_s[jj][0];
            ulonglong2 w0 = wq[0], w1 = wq[1], w4 = wq[4], w5 = wq[5];
            acc[0] = ffma2(w0.x, pd2, acc[0]); acc[1] = ffma2(w0.y, pd2, acc[1]);
            acc[2] = ffma2(w1.x, pd2, acc[2]); acc[3] = ffma2(w1.y, pd2, acc[3]);
            acc[0] = ffma2(w4.x, dl2, acc[0]); acc[1] = ffma2(w4.y, dl2, acc[1]);
            acc[2] = ffma2(w5.x, dl2, acc[2]); acc[3] = ffma2(w5.y, dl2, acc[3]);
        }
    }

    float h[8];
#pragma unroll
    for (int p = 0; p < 4; p++) {
        float2 t = unpk(acc[p]);
        h[2 * p] = t.x; h[2 * p + 1] = t.y;
    }

    // --- Phase D: log_softmax over d for each of the 8 rows
#pragma unroll
    for (int r = 0; r < 8; r++) {
        float m = h[r];
#pragma unroll
        for (int o = 16; o > 0; o >>= 1) m = fmaxf(m, __shfl_xor_sync(0xffffffffu, m, o));
        if (lane == 0) red[warp][r] = m;
    }
    __syncthreads();
    {
        float m = (lane < 8) ? red[lane][warp] : -3.4e38f;
#pragma unroll
        for (int o = 4; o > 0; o >>= 1) m = fmaxf(m, __shfl_xor_sync(0xffffffffu, m, o));
        if (lane == 0) mx[warp] = m;
    }
    __syncthreads();
#pragma unroll
    for (int r = 0; r < 8; r++) {
        float s = expf(h[r] - mx[r]);
#pragma unroll
        for (int o = 16; o > 0; o >>= 1) s += __shfl_xor_sync(0xffffffffu, s, o);
        if (lane == 0) red[warp][r] = s;
    }
    __syncthreads();
    {
        float s = (lane < 8) ? red[lane][warp] : 0.f;
#pragma unroll
        for (int o = 4; o > 0; o >>= 1) s += __shfl_xor_sync(0xffffffffu, s, o);
        if (lane == 0) lsz[warp] = logf(s);
    }
    __syncthreads();
#pragma unroll
    for (int r = 0; r < 8; r++)
        out[(size_t)(n0 + r) * 256 + d] = h[r] - mx[r] - lsz[r];
}

// ---------------------------------------------------------------------------
extern "C" void kernel_launch(void* const* d_in, const int* in_sizes, int n_in,
                              void* d_out, int out_size) {
    const float* x     = (const float*)d_in[0];
    const int*   spk   = (const int*)d_in[1];
    const float* Wa    = (const float*)d_in[2];
    const float* Wp    = (const float*)d_in[3];
    const float* Wsuc  = (const float*)d_in[4];
    const float* Wsame = (const float*)d_in[5];
    const float* Wdiff = (const float*)d_in[6];
    float* out = (float*)d_out;

    combine_kernel<<<(Dd * NC + 255) / 256, 256>>>(Wa, Wp, Wsuc, Wsame, Wdiff);

    dim3 gg(NC / BN, Nn / BM);
    sgemm_kernel<<<gg, 256>>>(x);

    attn_agg_kernel<<<Nn / 8, 256>>>(x, spk, out);
}